// round 8
// baseline (speedup 1.0000x reference)
#include <cuda_runtime.h>
#include <cstdint>

// Problem constants
#define Bb   8
#define Cch  128
#define Nn   2304      // 48*48
#define REDr 16
#define BM   128       // query tile rows per CTA
#define BN   64        // key tile per iteration
#define NTIL (Nn / BN) // 36
// smem strides (floats) — conflict-free fragment access
#define QSTR 132
#define KSTR 132
#define VSTR 136
#define PSTR 68
#define QK_STRIDE 132  // fp32 qkv-projection smem stride

// attn smem layout (float offsets)
#define OFF_Q    0
#define OFF_KHI  16896                 // 128*132
#define OFF_KLO  (OFF_KHI + 8448)     // 64*132
#define OFF_VS   (OFF_KLO + 8448)
#define OFF_PS   (OFF_VS  + 8704)     // 64*136
#define OFF_LSUM (OFF_PS  + 8704)     // 128*68
#define ATTN_FLOATS (OFF_LSUM + 256)
#define ATTN_SMEM (ATTN_FLOATS * 4)   // 205824 B

// Scratch (__device__ globals; no allocation allowed)
__device__ float g_q[Bb * Nn * Cch];   // [b][n][c]
__device__ float g_k[Bb * Nn * Cch];   // [b][n][c]
__device__ float g_v[Bb * Nn * Cch];   // [b][n][c]
__device__ float g_mean[Bb * Cch];
__device__ float g_y[Bb * Cch];

// Round-to-nearest tf32 (for 3xTF32 split)
__device__ __forceinline__ float to_tf32(float a) {
    float r;
    asm("cvt.rna.tf32.f32 %0, %1;" : "=f"(r) : "f"(a));
    return r;
}

// m16n8k8 tf32 mma. Thread t: gid=t>>2, tig=t&3.
// A (16x8 row): a0=(gid,tig) a1=(gid+8,tig) a2=(gid,tig+4) a3=(gid+8,tig+4)
// B (8x8 col):  b0=(k=tig,n=gid) b1=(k=tig+4,n=gid)
// D (16x8):     c0=(gid,2tig) c1=(gid,2tig+1) c2=(gid+8,2tig) c3=(gid+8,2tig+1)
__device__ __forceinline__ void mma_tf32(float& d0, float& d1, float& d2, float& d3,
                                         uint32_t a0, uint32_t a1, uint32_t a2, uint32_t a3,
                                         uint32_t b0, uint32_t b1)
{
    asm volatile("mma.sync.aligned.m16n8k8.row.col.f32.tf32.tf32.f32 "
                 "{%0,%1,%2,%3}, {%4,%5,%6,%7}, {%8,%9}, {%0,%1,%2,%3};"
                 : "+f"(d0), "+f"(d1), "+f"(d2), "+f"(d3)
                 : "r"(a0), "r"(a1), "r"(a2), "r"(a3), "r"(b0), "r"(b1));
}

// ---------------------------------------------------------------------------
// Kernel 1: QKV projection, fp32 FFMA (exact). q,k,v stored [b][n][c].
// ---------------------------------------------------------------------------
__global__ __launch_bounds__(256) void qkv_kernel(
    const float* __restrict__ x,
    const float* __restrict__ Wq, const float* __restrict__ bq,
    const float* __restrict__ Wk, const float* __restrict__ bk,
    const float* __restrict__ Wv, const float* __restrict__ bv)
{
    extern __shared__ float sm[];
    float* xs  = sm;                   // [128 ci][QK_STRIDE] cols = n
    float* wst = sm + 128 * QK_STRIDE; // [128 ci][QK_STRIDE] cols = o

    const int b   = blockIdx.y;
    const int n0  = blockIdx.x * 128;
    const int tid = threadIdx.x;
    const int ty  = tid >> 4;
    const int tx  = tid & 15;

    for (int i = tid; i < 128 * 128; i += 256) {
        int ci = i >> 7, n = i & 127;
        xs[ci * QK_STRIDE + n] = x[((size_t)b * Cch + ci) * Nn + n0 + n];
    }

    const float* Ws[3]   = {Wq, Wk, Wv};
    const float* bias[3] = {bq, bk, bv};
    float* outs[3]       = {g_q, g_k, g_v};

    for (int m = 0; m < 3; m++) {
        __syncthreads();
        const float* W = Ws[m];
        for (int i = tid; i < 128 * 128; i += 256) {
            int o = i >> 7, ci = i & 127;
            wst[ci * QK_STRIDE + o] = W[i];
        }
        __syncthreads();

        float acc[8][8];
        #pragma unroll
        for (int i = 0; i < 8; i++)
            #pragma unroll
            for (int u = 0; u < 8; u++) acc[i][u] = 0.f;

        #pragma unroll 4
        for (int ci = 0; ci < 128; ci++) {
            float4 w0 = *(const float4*)&wst[ci * QK_STRIDE + ty * 8];
            float4 w1 = *(const float4*)&wst[ci * QK_STRIDE + ty * 8 + 4];
            float4 x0 = *(const float4*)&xs [ci * QK_STRIDE + tx * 8];
            float4 x1 = *(const float4*)&xs [ci * QK_STRIDE + tx * 8 + 4];
            float wf[8] = {w0.x, w0.y, w0.z, w0.w, w1.x, w1.y, w1.z, w1.w};
            float xf[8] = {x0.x, x0.y, x0.z, x0.w, x1.x, x1.y, x1.z, x1.w};
            #pragma unroll
            for (int i = 0; i < 8; i++)
                #pragma unroll
                for (int u = 0; u < 8; u++)
                    acc[i][u] += wf[i] * xf[u];
        }

        float* outp = outs[m] + (size_t)b * Nn * Cch;
        float bvals[8];
        #pragma unroll
        for (int i = 0; i < 8; i++) bvals[i] = bias[m][ty * 8 + i];
        #pragma unroll
        for (int u = 0; u < 8; u++) {
            int n = n0 + tx * 8 + u;
            float4 s0 = {acc[0][u] + bvals[0], acc[1][u] + bvals[1],
                         acc[2][u] + bvals[2], acc[3][u] + bvals[3]};
            float4 s1 = {acc[4][u] + bvals[4], acc[5][u] + bvals[5],
                         acc[6][u] + bvals[6], acc[7][u] + bvals[7]};
            *(float4*)&outp[(size_t)n * Cch + ty * 8]     = s0;
            *(float4*)&outp[(size_t)n * Cch + ty * 8 + 4] = s1;
        }
    }
}

// ---------------------------------------------------------------------------
// Kernel 2: per-(b,c) spatial mean of x.
// ---------------------------------------------------------------------------
__global__ __launch_bounds__(128) void se_mean_kernel(const float* __restrict__ x)
{
    const int bc  = blockIdx.x;
    const int tid = threadIdx.x;
    __shared__ float red[128];
    float s = 0.f;
    for (int t = tid; t < Nn; t += 128) s += x[(size_t)bc * Nn + t];
    red[tid] = s;
    __syncthreads();
    for (int off = 64; off > 0; off >>= 1) {
        if (tid < off) red[tid] += red[tid + off];
        __syncthreads();
    }
    if (tid == 0) g_mean[bc] = red[0] * (1.f / (float)Nn);
}

// ---------------------------------------------------------------------------
// Kernel 3: SE MLP.
// ---------------------------------------------------------------------------
__global__ __launch_bounds__(128) void se_mlp_kernel(
    const float* __restrict__ w1, const float* __restrict__ w2)
{
    __shared__ float h[Bb][Cch / REDr];
    const int tid = threadIdx.x;
    if (tid < Bb * (Cch / REDr)) {
        int b = tid >> 3, r = tid & 7;
        float s = 0.f;
        for (int c = 0; c < Cch; c++) s += g_mean[b * Cch + c] * w1[r * Cch + c];
        h[b][r] = fmaxf(s, 0.f);
    }
    __syncthreads();
    for (int idx = tid; idx < Bb * Cch; idx += 128) {
        int b = idx >> 7, c = idx & 127;
        float s = 0.f;
        #pragma unroll
        for (int r = 0; r < Cch / REDr; r++) s += h[b][r] * w2[c * (Cch / REDr) + r];
        g_y[idx] = 1.f / (1.f + __expf(-s));
    }
}

// ---------------------------------------------------------------------------
// Kernel 4: flash attention, 512 threads / 16 warps.
// Warp pair (rg = wid>>1) shares 16 query rows; h = wid&1 selects:
//   S phase: key half (4 of 8 n-chunks)       -> 192 MMA/warp (3xTF32)
//   PV phase: channel half (8 of 16 chunks)   -> 64 MMA/warp (plain tf32)
// Q persists in smem (fp32), split hi/lo per k-chunk at use.
// Grid (18, 8) = 144 CTAs, 1 CTA/SM, 25% occupancy.
// ---------------------------------------------------------------------------
__global__ __launch_bounds__(512, 1) void attn_kernel(
    const float* __restrict__ x,
    const float* __restrict__ gamma,
    float* __restrict__ out)
{
    extern __shared__ float sm[];
    float* Qs   = sm + OFF_Q;
    float* Khi  = sm + OFF_KHI;
    float* Klo  = sm + OFF_KLO;
    float* Vs   = sm + OFF_VS;
    float* Ps   = sm + OFF_PS;
    float* lsum = sm + OFF_LSUM;

    const int b    = blockIdx.y;
    const int m0   = blockIdx.x * BM;
    const int tid  = threadIdx.x;
    const int wid  = tid >> 5;
    const int lane = tid & 31;
    const int gid  = lane >> 2;
    const int tig  = lane & 3;
    const int h    = wid & 1;        // half selector within the pair
    const int wr   = (wid >> 1) * 16; // query-row base (shared by the pair)

    const float* qb = g_q + (size_t)b * Nn * Cch;
    const float* kb = g_k + (size_t)b * Nn * Cch;
    const float* vb = g_v + (size_t)b * Nn * Cch;

    // Stage Q tile once (persists whole kernel).
    for (int i = tid; i < 128 * 32; i += 512) {
        int r = i >> 5, c4 = i & 31;
        *(float4*)&Qs[r * QSTR + c4 * 4] =
            *(const float4*)&qb[(size_t)(m0 + r) * Cch + c4 * 4];
    }

    float o_acc[8][4];
    #pragma unroll
    for (int n = 0; n < 8; n++) {
        o_acc[n][0] = 0.f; o_acc[n][1] = 0.f; o_acc[n][2] = 0.f; o_acc[n][3] = 0.f;
    }
    float l_lo = 0.f, l_hi = 0.f;   // partial row sums (this warp's key half)

    __syncthreads();  // Q ready (also covers first K staging ordering)

    for (int t = 0; t < NTIL; t++) {
        const int n0 = t * BN;
        // Stage K (split hi/lo) and V tiles.
        for (int i = tid; i < 64 * 32; i += 512) {
            int r = i >> 5, c4 = i & 31;
            float4 kv = *(const float4*)&kb[(size_t)(n0 + r) * Cch + c4 * 4];
            float4 khi, klo;
            khi.x = to_tf32(kv.x); klo.x = to_tf32(kv.x - khi.x);
            khi.y = to_tf32(kv.y); klo.y = to_tf32(kv.y - khi.y);
            khi.z = to_tf32(kv.z); klo.z = to_tf32(kv.z - khi.z);
            khi.w = to_tf32(kv.w); klo.w = to_tf32(kv.w - khi.w);
            *(float4*)&Khi[r * KSTR + c4 * 4] = khi;
            *(float4*)&Klo[r * KSTR + c4 * 4] = klo;
            *(float4*)&Vs [r * VSTR + c4 * 4] =
                *(const float4*)&vb[(size_t)(n0 + r) * Cch + c4 * 4];
        }
        __syncthreads();

        // S = Q K^T with 3xTF32 for this warp's key half.
        float sacc[4][4];
        #pragma unroll
        for (int n = 0; n < 4; n++) {
            sacc[n][0] = 0.f; sacc[n][1] = 0.f; sacc[n][2] = 0.f; sacc[n][3] = 0.f;
        }
        #pragma unroll
        for (int kc = 0; kc < 16; kc++) {
            float q0 = Qs[(wr + gid)     * QSTR + kc * 8 + tig];
            float q1 = Qs[(wr + gid + 8) * QSTR + kc * 8 + tig];
            float q2 = Qs[(wr + gid)     * QSTR + kc * 8 + tig + 4];
            float q3 = Qs[(wr + gid + 8) * QSTR + kc * 8 + tig + 4];
            float h0 = to_tf32(q0), h1 = to_tf32(q1), h2 = to_tf32(q2), h3 = to_tf32(q3);
            uint32_t qh[4] = {__float_as_uint(h0), __float_as_uint(h1),
                              __float_as_uint(h2), __float_as_uint(h3)};
            uint32_t ql[4] = {__float_as_uint(to_tf32(q0 - h0)), __float_as_uint(to_tf32(q1 - h1)),
                              __float_as_uint(to_tf32(q2 - h2)), __float_as_uint(to_tf32(q3 - h3))};
            #pragma unroll
            for (int j = 0; j < 4; j++) {
                int nch = h * 4 + j;
                int krow = (nch * 8 + gid) * KSTR + kc * 8 + tig;
                uint32_t bh0 = __float_as_uint(Khi[krow]);
                uint32_t bh1 = __float_as_uint(Khi[krow + 4]);
                uint32_t bl0 = __float_as_uint(Klo[krow]);
                uint32_t bl1 = __float_as_uint(Klo[krow + 4]);
                mma_tf32(sacc[j][0], sacc[j][1], sacc[j][2], sacc[j][3],
                         qh[0], qh[1], qh[2], qh[3], bh0, bh1);
                mma_tf32(sacc[j][0], sacc[j][1], sacc[j][2], sacc[j][3],
                         ql[0], ql[1], ql[2], ql[3], bh0, bh1);
                mma_tf32(sacc[j][0], sacc[j][1], sacc[j][2], sacc[j][3],
                         qh[0], qh[1], qh[2], qh[3], bl0, bl1);
            }
        }

        // exp, partial row sums, stash P (this warp's key-half columns).
        #pragma unroll
        for (int j = 0; j < 4; j++) {
            int nch = h * 4 + j;
            float p0 = __expf(sacc[j][0]), p1 = __expf(sacc[j][1]);
            float p2 = __expf(sacc[j][2]), p3 = __expf(sacc[j][3]);
            l_lo += p0 + p1;
            l_hi += p2 + p3;
            *(float2*)&Ps[(wr + gid)     * PSTR + nch * 8 + 2 * tig] = make_float2(p0, p1);
            *(float2*)&Ps[(wr + gid + 8) * PSTR + nch * 8 + 2 * tig] = make_float2(p2, p3);
        }
        __syncthreads();   // both halves of P visible to the pair

        // Reload P as A-frags over the FULL key range.
        uint32_t pf[8][4];
        #pragma unroll
        for (int kc = 0; kc < 8; kc++) {
            pf[kc][0] = __float_as_uint(Ps[(wr + gid)     * PSTR + kc * 8 + tig]);
            pf[kc][1] = __float_as_uint(Ps[(wr + gid + 8) * PSTR + kc * 8 + tig]);
            pf[kc][2] = __float_as_uint(Ps[(wr + gid)     * PSTR + kc * 8 + tig + 4]);
            pf[kc][3] = __float_as_uint(Ps[(wr + gid + 8) * PSTR + kc * 8 + tig + 4]);
        }

        // O += P V for this warp's channel half (plain tf32).
        #pragma unroll
        for (int j = 0; j < 8; j++) {
            int nch = h * 8 + j;
            #pragma unroll
            for (int kc = 0; kc < 8; kc++) {
                uint32_t b0 = __float_as_uint(Vs[(kc * 8 + tig)     * VSTR + nch * 8 + gid]);
                uint32_t b1 = __float_as_uint(Vs[(kc * 8 + tig + 4) * VSTR + nch * 8 + gid]);
                mma_tf32(o_acc[j][0], o_acc[j][1], o_acc[j][2], o_acc[j][3],
                         pf[kc][0], pf[kc][1], pf[kc][2], pf[kc][3], b0, b1);
            }
        }
        __syncthreads();   // Khi/Klo/Vs/Ps free to overwrite next tile
    }

    // Combine partial row sums: quad reduce, then across the warp pair.
    l_lo += __shfl_xor_sync(0xFFFFFFFF, l_lo, 1);
    l_lo += __shfl_xor_sync(0xFFFFFFFF, l_lo, 2);
    l_hi += __shfl_xor_sync(0xFFFFFFFF, l_hi, 1);
    l_hi += __shfl_xor_sync(0xFFFFFFFF, l_hi, 2);
    if (tig == 0) {
        lsum[(wr + gid)     * 2 + h] = l_lo;
        lsum[(wr + gid + 8) * 2 + h] = l_hi;
    }
    __syncthreads();
    const float inv_lo = 1.f / (lsum[(wr + gid)     * 2] + lsum[(wr + gid)     * 2 + 1]);
    const float inv_hi = 1.f / (lsum[(wr + gid + 8) * 2] + lsum[(wr + gid + 8) * 2 + 1]);

    // Epilogue: out[b][c][i] = gamma * O[i][c]/l[i] + x[b][c][i] * y[b][c]
    const float g = gamma[0];
    const int i_lo = m0 + wr + gid;
    const int i_hi = i_lo + 8;
    const float* yb = g_y + b * Cch;
    #pragma unroll
    for (int j = 0; j < 8; j++) {
        int nch = h * 8 + j;
        int c0 = nch * 8 + 2 * tig;
        int c1 = c0 + 1;
        size_t i00 = ((size_t)b * Cch + c0) * Nn;
        size_t i01 = ((size_t)b * Cch + c1) * Nn;
        out[i00 + i_lo] = g * (o_acc[j][0] * inv_lo) + x[i00 + i_lo] * yb[c0];
        out[i01 + i_lo] = g * (o_acc[j][1] * inv_lo) + x[i01 + i_lo] * yb[c1];
        out[i00 + i_hi] = g * (o_acc[j][2] * inv_hi) + x[i00 + i_hi] * yb[c0];
        out[i01 + i_hi] = g * (o_acc[j][3] * inv_hi) + x[i01 + i_hi] * yb[c1];
    }
}

// ---------------------------------------------------------------------------
extern "C" void kernel_launch(void* const* d_in, const int* in_sizes, int n_in,
                              void* d_out, int out_size)
{
    const float* x     = (const float*)d_in[0];
    const float* Wq    = (const float*)d_in[1];
    const float* bq    = (const float*)d_in[2];
    const float* Wk    = (const float*)d_in[3];
    const float* bk    = (const float*)d_in[4];
    const float* Wv    = (const float*)d_in[5];
    const float* bv    = (const float*)d_in[6];
    const float* se_w1 = (const float*)d_in[7];
    const float* se_w2 = (const float*)d_in[8];
    const float* gamma = (const float*)d_in[9];
    float* out = (float*)d_out;

    const int QKV_SMEM = 2 * 128 * QK_STRIDE * (int)sizeof(float);   // 135168

    cudaFuncSetAttribute(qkv_kernel,  cudaFuncAttributeMaxDynamicSharedMemorySize, QKV_SMEM);
    cudaFuncSetAttribute(attn_kernel, cudaFuncAttributeMaxDynamicSharedMemorySize, ATTN_SMEM);

    qkv_kernel<<<dim3(Nn / 128, Bb), 256, QKV_SMEM>>>(x, Wq, bq, Wk, bk, Wv, bv);
    se_mean_kernel<<<Bb * Cch, 128>>>(x);
    se_mlp_kernel<<<1, 128>>>(se_w1, se_w2);
    attn_kernel<<<dim3(Nn / BM, Bb), 512, ATTN_SMEM>>>(x, gamma, out);
}

// round 9
// speedup vs baseline: 1.2352x; 1.2352x over previous
#include <cuda_runtime.h>
#include <cuda_bf16.h>
#include <cstdint>

// Problem constants
#define Bb   8
#define Cch  128
#define Nn   2304      // 48*48
#define REDr 16
#define BM   128       // query tile rows per CTA
#define BN   64        // key tile per iteration
#define NTIL (Nn / BN) // 36
#define QK_STRIDE 132  // fp32 qkv-projection smem stride

// attn smem (uint32 word offsets). bf16 pairs packed in uint32.
// Q/K rows are [row][c2] (c2 = channel/2, 64 words + 4 pad = 68)
// Vt rows are [chan][key2] (32 words + 4 pad = 36); Ps same shape class.
#define KSU  68
#define VSU  36
#define PSU  36
#define U_QHI 0
#define U_QLO (U_QHI + 128 * KSU)   // 8704
#define U_KHI (U_QLO + 128 * KSU)   // 17408
#define U_KLO (U_KHI + 64 * KSU)    // 21760
#define U_VHI (U_KLO + 64 * KSU)    // 26112
#define U_VLO (U_VHI + 128 * VSU)   // 30720
#define U_PS  (U_VLO + 128 * VSU)   // 35328
#define ATTN_WORDS (U_PS + 128 * PSU)     // 39936
#define ATTN_SMEM (ATTN_WORDS * 4)        // 159744 B

// Scratch (__device__ globals; no allocation allowed)
__device__ float g_q [Bb * Nn * Cch];   // [b][n][c]
__device__ float g_k [Bb * Nn * Cch];   // [b][n][c]
__device__ float g_vt[Bb * Cch * Nn];   // [b][c][n]  (V transposed)
__device__ float g_mean[Bb * Cch];
__device__ float g_y[Bb * Cch];

// pack two floats to bf16x2 (rn): low half = 'lo' (even index), high = 'hi'
__device__ __forceinline__ uint32_t pack_bf16(float lo, float hi) {
    uint32_t r;
    asm("cvt.rn.bf16x2.f32 %0, %1, %2;" : "=r"(r) : "f"(hi), "f"(lo));
    return r;
}
__device__ __forceinline__ float rb16(float a) {   // round to bf16, back to f32
    return __bfloat162float(__float2bfloat16(a));
}

// m16n8k16 bf16 mma. Thread t: gid=t>>2, tig=t&3.
// A (16x16 row): a0={A[gid][2tig],A[gid][2tig+1]} a1=row gid+8; a2/a3: k+8
// B (16x8 col):  b0={B[2tig][gid],B[2tig+1][gid]} b1: k+8
// D (16x8):      c0=(gid,2tig) c1=(gid,2tig+1) c2=(gid+8,2tig) c3=(gid+8,2tig+1)
__device__ __forceinline__ void mma_bf16(float& d0, float& d1, float& d2, float& d3,
                                         uint32_t a0, uint32_t a1, uint32_t a2, uint32_t a3,
                                         uint32_t b0, uint32_t b1)
{
    asm volatile("mma.sync.aligned.m16n8k16.row.col.f32.bf16.bf16.f32 "
                 "{%0,%1,%2,%3}, {%4,%5,%6,%7}, {%8,%9}, {%0,%1,%2,%3};"
                 : "+f"(d0), "+f"(d1), "+f"(d2), "+f"(d3)
                 : "r"(a0), "r"(a1), "r"(a2), "r"(a3), "r"(b0), "r"(b1));
}

// ---------------------------------------------------------------------------
// Kernel 1: QKV projection, fp32 FFMA (exact). q,k -> [b][n][c]; v -> [b][c][n].
// ---------------------------------------------------------------------------
__global__ __launch_bounds__(256) void qkv_kernel(
    const float* __restrict__ x,
    const float* __restrict__ Wq, const float* __restrict__ bq,
    const float* __restrict__ Wk, const float* __restrict__ bk,
    const float* __restrict__ Wv, const float* __restrict__ bv)
{
    extern __shared__ float sm[];
    float* xs  = sm;                   // [128 ci][QK_STRIDE] cols = n
    float* wst = sm + 128 * QK_STRIDE; // [128 ci][QK_STRIDE] cols = o

    const int b   = blockIdx.y;
    const int n0  = blockIdx.x * 128;
    const int tid = threadIdx.x;
    const int ty  = tid >> 4;
    const int tx  = tid & 15;

    for (int i = tid; i < 128 * 128; i += 256) {
        int ci = i >> 7, n = i & 127;
        xs[ci * QK_STRIDE + n] = x[((size_t)b * Cch + ci) * Nn + n0 + n];
    }

    const float* Ws[3]   = {Wq, Wk, Wv};
    const float* bias[3] = {bq, bk, bv};

    for (int m = 0; m < 3; m++) {
        __syncthreads();
        const float* W = Ws[m];
        for (int i = tid; i < 128 * 128; i += 256) {
            int o = i >> 7, ci = i & 127;
            wst[ci * QK_STRIDE + o] = W[i];
        }
        __syncthreads();

        float acc[8][8];
        #pragma unroll
        for (int i = 0; i < 8; i++)
            #pragma unroll
            for (int u = 0; u < 8; u++) acc[i][u] = 0.f;

        #pragma unroll 4
        for (int ci = 0; ci < 128; ci++) {
            float4 w0 = *(const float4*)&wst[ci * QK_STRIDE + ty * 8];
            float4 w1 = *(const float4*)&wst[ci * QK_STRIDE + ty * 8 + 4];
            float4 x0 = *(const float4*)&xs [ci * QK_STRIDE + tx * 8];
            float4 x1 = *(const float4*)&xs [ci * QK_STRIDE + tx * 8 + 4];
            float wf[8] = {w0.x, w0.y, w0.z, w0.w, w1.x, w1.y, w1.z, w1.w};
            float xf[8] = {x0.x, x0.y, x0.z, x0.w, x1.x, x1.y, x1.z, x1.w};
            #pragma unroll
            for (int i = 0; i < 8; i++)
                #pragma unroll
                for (int u = 0; u < 8; u++)
                    acc[i][u] += wf[i] * xf[u];
        }

        float bvals[8];
        #pragma unroll
        for (int i = 0; i < 8; i++) bvals[i] = bias[m][ty * 8 + i];

        if (m < 2) {   // q,k: [b][n][c]
            float* outp = (m == 0 ? g_q : g_k) + (size_t)b * Nn * Cch;
            #pragma unroll
            for (int u = 0; u < 8; u++) {
                int n = n0 + tx * 8 + u;
                float4 s0 = {acc[0][u] + bvals[0], acc[1][u] + bvals[1],
                             acc[2][u] + bvals[2], acc[3][u] + bvals[3]};
                float4 s1 = {acc[4][u] + bvals[4], acc[5][u] + bvals[5],
                             acc[6][u] + bvals[6], acc[7][u] + bvals[7]};
                *(float4*)&outp[(size_t)n * Cch + ty * 8]     = s0;
                *(float4*)&outp[(size_t)n * Cch + ty * 8 + 4] = s1;
            }
        } else {       // v: transposed [b][c][n]
            float* outp = g_vt + (size_t)b * Cch * Nn;
            #pragma unroll
            for (int i = 0; i < 8; i++) {
                int c = ty * 8 + i;
                float bb = bvals[i];
                float4 s0 = {acc[i][0] + bb, acc[i][1] + bb, acc[i][2] + bb, acc[i][3] + bb};
                float4 s1 = {acc[i][4] + bb, acc[i][5] + bb, acc[i][6] + bb, acc[i][7] + bb};
                *(float4*)&outp[(size_t)c * Nn + n0 + tx * 8]     = s0;
                *(float4*)&outp[(size_t)c * Nn + n0 + tx * 8 + 4] = s1;
            }
        }
    }
}

// ---------------------------------------------------------------------------
// Kernel 2: per-(b,c) spatial mean of x.
// ---------------------------------------------------------------------------
__global__ __launch_bounds__(128) void se_mean_kernel(const float* __restrict__ x)
{
    const int bc  = blockIdx.x;
    const int tid = threadIdx.x;
    __shared__ float red[128];
    float s = 0.f;
    for (int t = tid; t < Nn; t += 128) s += x[(size_t)bc * Nn + t];
    red[tid] = s;
    __syncthreads();
    for (int off = 64; off > 0; off >>= 1) {
        if (tid < off) red[tid] += red[tid + off];
        __syncthreads();
    }
    if (tid == 0) g_mean[bc] = red[0] * (1.f / (float)Nn);
}

// ---------------------------------------------------------------------------
// Kernel 3: SE MLP.
// ---------------------------------------------------------------------------
__global__ __launch_bounds__(128) void se_mlp_kernel(
    const float* __restrict__ w1, const float* __restrict__ w2)
{
    __shared__ float h[Bb][Cch / REDr];
    const int tid = threadIdx.x;
    if (tid < Bb * (Cch / REDr)) {
        int b = tid >> 3, r = tid & 7;
        float s = 0.f;
        for (int c = 0; c < Cch; c++) s += g_mean[b * Cch + c] * w1[r * Cch + c];
        h[b][r] = fmaxf(s, 0.f);
    }
    __syncthreads();
    for (int idx = tid; idx < Bb * Cch; idx += 128) {
        int b = idx >> 7, c = idx & 127;
        float s = 0.f;
        #pragma unroll
        for (int r = 0; r < Cch / REDr; r++) s += h[b][r] * w2[c * (Cch / REDr) + r];
        g_y[idx] = 1.f / (1.f + __expf(-s));
    }
}

// ---------------------------------------------------------------------------
// Kernel 4: flash attention, bf16x3 S-path + bf16-split PV.
// 256 threads / 8 warps (proven R6 skeleton); warp owns 16 query rows.
// S = (Qhi+Qlo)(Khi+Klo)^T via hi*hi + lo*hi + hi*lo  (error ~3e-5)
// P -> bf16 (l summed from ROUNDED p for ratio consistency)
// O += P*(Vhi+Vlo) (V exact to 2^-17, unbiased)
// Grid (18, 8) = 144 CTAs, 1 wave.
// ---------------------------------------------------------------------------
__global__ __launch_bounds__(256, 1) void attn_kernel(
    const float* __restrict__ x,
    const float* __restrict__ gamma,
    float* __restrict__ out)
{
    extern __shared__ uint32_t smu[];

    const int b    = blockIdx.y;
    const int m0   = blockIdx.x * BM;
    const int tid  = threadIdx.x;
    const int wid  = tid >> 5;
    const int lane = tid & 31;
    const int gid  = lane >> 2;
    const int tig  = lane & 3;
    const int wr   = wid * 16;

    const float* qb  = g_q  + (size_t)b * Nn * Cch;
    const float* kb  = g_k  + (size_t)b * Nn * Cch;
    const float* vtb = g_vt + (size_t)b * Cch * Nn;

    // Stage Q once: [row][c2] bf16 pairs, hi and lo planes.
    for (int i = tid; i < 128 * 32; i += 256) {
        int r = i >> 5, c4 = i & 31;
        float4 q = *(const float4*)&qb[(size_t)(m0 + r) * Cch + c4 * 4];
        float h0 = rb16(q.x), h1 = rb16(q.y), h2 = rb16(q.z), h3 = rb16(q.w);
        uint2 hiw = {pack_bf16(h0, h1), pack_bf16(h2, h3)};
        uint2 low = {pack_bf16(q.x - h0, q.y - h1), pack_bf16(q.z - h2, q.w - h3)};
        *(uint2*)&smu[U_QHI + r * KSU + c4 * 2] = hiw;
        *(uint2*)&smu[U_QLO + r * KSU + c4 * 2] = low;
    }

    float o_acc[16][4];
    #pragma unroll
    for (int n = 0; n < 16; n++) {
        o_acc[n][0] = 0.f; o_acc[n][1] = 0.f; o_acc[n][2] = 0.f; o_acc[n][3] = 0.f;
    }
    float l_lo = 0.f, l_hi = 0.f;   // row sums (rows wr+gid / wr+gid+8)

    __syncthreads();

    for (int t = 0; t < NTIL; t++) {
        const int n0 = t * BN;
        // Stage K [key][c2] (hi/lo) — 64 rows x 32 float4
        for (int i = tid; i < 64 * 32; i += 256) {
            int r = i >> 5, c4 = i & 31;
            float4 k = *(const float4*)&kb[(size_t)(n0 + r) * Cch + c4 * 4];
            float h0 = rb16(k.x), h1 = rb16(k.y), h2 = rb16(k.z), h3 = rb16(k.w);
            uint2 hiw = {pack_bf16(h0, h1), pack_bf16(h2, h3)};
            uint2 low = {pack_bf16(k.x - h0, k.y - h1), pack_bf16(k.z - h2, k.w - h3)};
            *(uint2*)&smu[U_KHI + r * KSU + c4 * 2] = hiw;
            *(uint2*)&smu[U_KLO + r * KSU + c4 * 2] = low;
        }
        // Stage Vt [chan][key2] (hi/lo) — 128 rows x 16 float4 (64 keys)
        for (int i = tid; i < 128 * 16; i += 256) {
            int c = i >> 4, n4 = i & 15;
            float4 v = *(const float4*)&vtb[(size_t)c * Nn + n0 + n4 * 4];
            float h0 = rb16(v.x), h1 = rb16(v.y), h2 = rb16(v.z), h3 = rb16(v.w);
            uint2 hiw = {pack_bf16(h0, h1), pack_bf16(h2, h3)};
            uint2 low = {pack_bf16(v.x - h0, v.y - h1), pack_bf16(v.z - h2, v.w - h3)};
            *(uint2*)&smu[U_VHI + c * VSU + n4 * 2] = hiw;
            *(uint2*)&smu[U_VLO + c * VSU + n4 * 2] = low;
        }
        __syncthreads();

        // ---- S = Q K^T (bf16x3), this warp's 16 rows x 64 keys ----
        float sacc[8][4];
        #pragma unroll
        for (int n = 0; n < 8; n++) {
            sacc[n][0] = 0.f; sacc[n][1] = 0.f; sacc[n][2] = 0.f; sacc[n][3] = 0.f;
        }
        #pragma unroll
        for (int kc = 0; kc < 8; kc++) {   // 16 channels per step
            uint32_t qh0 = smu[U_QHI + (wr + gid)     * KSU + kc * 8 + tig];
            uint32_t qh1 = smu[U_QHI + (wr + gid + 8) * KSU + kc * 8 + tig];
            uint32_t qh2 = smu[U_QHI + (wr + gid)     * KSU + kc * 8 + tig + 4];
            uint32_t qh3 = smu[U_QHI + (wr + gid + 8) * KSU + kc * 8 + tig + 4];
            uint32_t ql0 = smu[U_QLO + (wr + gid)     * KSU + kc * 8 + tig];
            uint32_t ql1 = smu[U_QLO + (wr + gid + 8) * KSU + kc * 8 + tig];
            uint32_t ql2 = smu[U_QLO + (wr + gid)     * KSU + kc * 8 + tig + 4];
            uint32_t ql3 = smu[U_QLO + (wr + gid + 8) * KSU + kc * 8 + tig + 4];
            #pragma unroll
            for (int nch = 0; nch < 8; nch++) {
                int krow = (nch * 8 + gid) * KSU + kc * 8 + tig;
                uint32_t bh0 = smu[U_KHI + krow];
                uint32_t bh1 = smu[U_KHI + krow + 4];
                uint32_t bl0 = smu[U_KLO + krow];
                uint32_t bl1 = smu[U_KLO + krow + 4];
                mma_bf16(sacc[nch][0], sacc[nch][1], sacc[nch][2], sacc[nch][3],
                         qh0, qh1, qh2, qh3, bh0, bh1);
                mma_bf16(sacc[nch][0], sacc[nch][1], sacc[nch][2], sacc[nch][3],
                         ql0, ql1, ql2, ql3, bh0, bh1);
                mma_bf16(sacc[nch][0], sacc[nch][1], sacc[nch][2], sacc[nch][3],
                         qh0, qh1, qh2, qh3, bl0, bl1);
            }
        }

        // ---- softmax numerator: p = exp(s), rounded to bf16; l from rounded p ----
        #pragma unroll
        for (int nch = 0; nch < 8; nch++) {
            float p0 = __expf(sacc[nch][0]), p1 = __expf(sacc[nch][1]);
            float p2 = __expf(sacc[nch][2]), p3 = __expf(sacc[nch][3]);
            // consistency: l must sum the SAME values PV will consume
            l_lo += rb16(p0) + rb16(p1);
            l_hi += rb16(p2) + rb16(p3);
            smu[U_PS + (wr + gid)     * PSU + nch * 4 + tig] = pack_bf16(p0, p1);
            smu[U_PS + (wr + gid + 8) * PSU + nch * 4 + tig] = pack_bf16(p2, p3);
        }
        __syncwarp();   // Ps rows are warp-private

        // Reload P as A-frags (4 k16-chunks over 64 keys)
        uint32_t pf[4][4];
        #pragma unroll
        for (int kc = 0; kc < 4; kc++) {
            pf[kc][0] = smu[U_PS + (wr + gid)     * PSU + kc * 8 + tig];
            pf[kc][1] = smu[U_PS + (wr + gid + 8) * PSU + kc * 8 + tig];
            pf[kc][2] = smu[U_PS + (wr + gid)     * PSU + kc * 8 + tig + 4];
            pf[kc][3] = smu[U_PS + (wr + gid + 8) * PSU + kc * 8 + tig + 4];
        }

        // ---- O += P (Vhi + Vlo) ----
        #pragma unroll
        for (int nch = 0; nch < 16; nch++) {
            #pragma unroll
            for (int kc = 0; kc < 4; kc++) {
                int vrow = (nch * 8 + gid) * VSU + kc * 8 + tig;
                uint32_t vh0 = smu[U_VHI + vrow];
                uint32_t vh1 = smu[U_VHI + vrow + 4];
                uint32_t vl0 = smu[U_VLO + vrow];
                uint32_t vl1 = smu[U_VLO + vrow + 4];
                mma_bf16(o_acc[nch][0], o_acc[nch][1], o_acc[nch][2], o_acc[nch][3],
                         pf[kc][0], pf[kc][1], pf[kc][2], pf[kc][3], vh0, vh1);
                mma_bf16(o_acc[nch][0], o_acc[nch][1], o_acc[nch][2], o_acc[nch][3],
                         pf[kc][0], pf[kc][1], pf[kc][2], pf[kc][3], vl0, vl1);
            }
        }
        __syncthreads();   // K/V/Ps free for next tile
    }

    // Row sums across the quad (lanes with same gid, tig 0..3)
    l_lo += __shfl_xor_sync(0xFFFFFFFF, l_lo, 1);
    l_lo += __shfl_xor_sync(0xFFFFFFFF, l_lo, 2);
    l_hi += __shfl_xor_sync(0xFFFFFFFF, l_hi, 1);
    l_hi += __shfl_xor_sync(0xFFFFFFFF, l_hi, 2);
    const float inv_lo = 1.f / l_lo;
    const float inv_hi = 1.f / l_hi;

    // Epilogue: out[b][c][i] = gamma * O[i][c]/l[i] + x[b][c][i] * y[b][c]
    const float g = gamma[0];
    const int i_lo = m0 + wr + gid;
    const int i_hi = i_lo + 8;
    const float* yb = g_y + b * Cch;
    #pragma unroll
    for (int nch = 0; nch < 16; nch++) {
        int c0 = nch * 8 + 2 * tig;
        int c1 = c0 + 1;
        size_t i00 = ((size_t)b * Cch + c0) * Nn;
        size_t i01 = ((size_t)b * Cch + c1) * Nn;
        out[i00 + i_lo] = g * (o_acc[nch][0] * inv_lo) + x[i00 + i_lo] * yb[c0];
        out[i01 + i_lo] = g * (o_acc[nch][1] * inv_lo) + x[i01 + i_lo] * yb[c1];
        out[i00 + i_hi] = g * (o_acc[nch][2] * inv_hi) + x[i00 + i_hi] * yb[c0];
        out[i01 + i_hi] = g * (o_acc[nch][3] * inv_hi) + x[i01 + i_hi] * yb[c1];
    }
}

// ---------------------------------------------------------------------------
extern "C" void kernel_launch(void* const* d_in, const int* in_sizes, int n_in,
                              void* d_out, int out_size)
{
    const float* x     = (const float*)d_in[0];
    const float* Wq    = (const float*)d_in[1];
    const float* bq    = (const float*)d_in[2];
    const float* Wk    = (const float*)d_in[3];
    const float* bk    = (const float*)d_in[4];
    const float* Wv    = (const float*)d_in[5];
    const float* bv    = (const float*)d_in[6];
    const float* se_w1 = (const float*)d_in[7];
    const float* se_w2 = (const float*)d_in[8];
    const float* gamma = (const float*)d_in[9];
    float* out = (float*)d_out;

    const int QKV_SMEM = 2 * 128 * QK_STRIDE * (int)sizeof(float);   // 135168

    cudaFuncSetAttribute(qkv_kernel,  cudaFuncAttributeMaxDynamicSharedMemorySize, QKV_SMEM);
    cudaFuncSetAttribute(attn_kernel, cudaFuncAttributeMaxDynamicSharedMemorySize, ATTN_SMEM);

    qkv_kernel<<<dim3(Nn / 128, Bb), 256, QKV_SMEM>>>(x, Wq, bq, Wk, bk, Wv, bv);
    se_mean_kernel<<<Bb * Cch, 128>>>(x);
    se_mlp_kernel<<<1, 128>>>(se_w1, se_w2);
    attn_kernel<<<dim3(Nn / BM, Bb), 256, ATTN_SMEM>>>(x, gamma, out);
}